// round 15
// baseline (speedup 1.0000x reference)
#include <cuda_runtime.h>
#include <cuda_bf16.h>
#include <float.h>
#include <cstdint>

#define NB 8
#define NS 4096
#define ND 256
#define NR 512
#define NC 2048
#define S1 (NS + 1)

#define BK 16
#define LDSP 132

// ---- mma staging (bf16 3-split, 3 buffers) ----
#define ABLK 12288
#define BBLK 12288
#define STAGE (ABLK + BBLK)
#define SMEM_MMA (3 * STAGE)    // 73728

#define NSLICE 8                // c-slices per s-tile

// k_emb dynamic smem: GEMM region (33792B) vs fragment staging (16*769*8 = 98432B)
#define CI_STRIDE 769           // uint2 elems per ci chunk (768 + 1 pad)
#define SMEM_EMBF (16 * CI_STRIDE * 8)   // 98432

// ---------------- scratch ----------------------------------------------------
__device__ float  g_t[NB * NR];
__device__ float  g_P[NB * ND * NR];
__device__ float  g_embT[(size_t)NB * NC * ND];
__device__ float  g_esq[NB * NC];
__device__ float  g_qsq[NB * NS];
__device__ int    g_idx[NB * NS];
__device__ int    g_hist[NB * NC];
__device__ double g_msep[256];
__device__ float  g_pminv[(size_t)NB * NS * NSLICE];
__device__ int    g_pmini[(size_t)NB * NS * NSLICE];
// fragment-ordered bf16 splits: A (pos) 16B/lane, B (embT) 8B/lane
__device__ uint4  g_pxspF[(size_t)NB * 256 * 16 * 3 * 32];
__device__ uint2  g_ebspF[(size_t)NB * 256 * 16 * 3 * 32];

// ---------------- f32x2 helpers (k_emb) --------------------------------------
__device__ __forceinline__ unsigned long long pack2(float lo, float hi) {
    unsigned long long r;
    asm("mov.b64 %0, {%1, %2};" : "=l"(r) : "f"(lo), "f"(hi));
    return r;
}
__device__ __forceinline__ void unpack2(unsigned long long v, float& lo, float& hi) {
    asm("mov.b64 {%0, %1}, %2;" : "=f"(lo), "=f"(hi) : "l"(v));
}
#define FMA2(d, a, b) asm("fma.rn.f32x2 %0, %1, %2, %0;" : "+l"(d) : "l"(a), "l"(b))

__device__ __forceinline__ void mma_tile(unsigned aAddr, unsigned bAddr,
                                         unsigned long long acc[4][8]) {
#pragma unroll
    for (int kk = 0; kk < BK; kk++) {
        unsigned long long a01, a23, a45, a67;
        asm("ld.shared.v2.b64 {%0,%1}, [%2];"
            : "=l"(a01), "=l"(a23) : "r"(aAddr + kk * (LDSP * 4)));
        asm("ld.shared.v2.b64 {%0,%1}, [%2];"
            : "=l"(a45), "=l"(a67) : "r"(aAddr + kk * (LDSP * 4) + 16));
        float b0, b1, b2, b3, b4, b5, b6, b7;
        asm("ld.shared.v4.b32 {%0,%1,%2,%3}, [%4];"
            : "=f"(b0), "=f"(b1), "=f"(b2), "=f"(b3) : "r"(bAddr + kk * (LDSP * 4)));
        asm("ld.shared.v4.b32 {%0,%1,%2,%3}, [%4];"
            : "=f"(b4), "=f"(b5), "=f"(b6), "=f"(b7) : "r"(bAddr + kk * (LDSP * 4) + 16));
        float bs[8] = {b0, b1, b2, b3, b4, b5, b6, b7};
#pragma unroll
        for (int j = 0; j < 8; j++) {
            unsigned long long bb = pack2(bs[j], bs[j]);
            FMA2(acc[0][j], a01, bb);
            FMA2(acc[1][j], a23, bb);
            FMA2(acc[2][j], a45, bb);
            FMA2(acc[3][j], a67, bb);
        }
    }
}

// ---------------- bf16 3-way split helpers -----------------------------------
__device__ __forceinline__ void split3u(float v, unsigned short h[3]) {
    __nv_bfloat16 b1 = __float2bfloat16(v);
    float r = v - __bfloat162float(b1);
    __nv_bfloat16 b2 = __float2bfloat16(r);
    float r2 = r - __bfloat162float(b2);
    __nv_bfloat16 b3 = __float2bfloat16(r2);
    h[0] = __bfloat16_as_ushort(b1);
    h[1] = __bfloat16_as_ushort(b2);
    h[2] = __bfloat16_as_ushort(b3);
}

// ---------------- t[b,r] + zero fold -----------------------------------------
__global__ void k_t(const float* __restrict__ x, const float* __restrict__ cls_w) {
    int b = blockIdx.x;
    int r = threadIdx.x;
    // fold: zero hist/msep (grid covers NB*NR = 4096 threads)
    int gt = b * NR + r;
    for (int i = gt; i < NB * NC; i += NB * NR) g_hist[i] = 0;
    if (gt < 256) g_msep[gt] = 0.0;

    __shared__ float cls[ND];
    if (r < ND) cls[r] = x[(size_t)b * S1 * ND + r];
    __syncthreads();
    float acc = 0.f;
#pragma unroll 8
    for (int d = 0; d < ND; d++) acc = fmaf(cls[d], cls_w[d * NR + r], acc);
    g_t[b * NR + r] = acc;
}

// ---------------- softmax (FROZEN) -------------------------------------------
__global__ void k_softmax(const float* __restrict__ x, const float* __restrict__ cls_b) {
    int d = blockIdx.x, b = blockIdx.y;
    int r = threadIdx.x;
    float clsd = x[(size_t)b * S1 * ND + d];
    float logit = fmaf(clsd, g_t[b * NR + r], cls_b[r]);

    __shared__ float sred[16];
    float m = logit;
#pragma unroll
    for (int o = 16; o; o >>= 1) m = fmaxf(m, __shfl_xor_sync(0xffffffffu, m, o));
    if ((r & 31) == 0) sred[r >> 5] = m;
    __syncthreads();
    if (r < 32) {
        float v = (r < 16) ? sred[r] : -FLT_MAX;
#pragma unroll
        for (int o = 16; o; o >>= 1) v = fmaxf(v, __shfl_xor_sync(0xffffffffu, v, o));
        if (r == 0) sred[0] = v;
    }
    __syncthreads();
    m = sred[0];
    float e = expf(logit - m);
    __syncthreads();
    float s = e;
#pragma unroll
    for (int o = 16; o; o >>= 1) s += __shfl_xor_sync(0xffffffffu, s, o);
    if ((r & 31) == 0) sred[r >> 5] = s;
    __syncthreads();
    if (r < 32) {
        float v = (r < 16) ? sred[r] : 0.f;
#pragma unroll
        for (int o = 16; o; o >>= 1) v += __shfl_xor_sync(0xffffffffu, v, o);
        if (r == 0) sred[0] = v;
    }
    __syncthreads();
    g_P[((size_t)b * ND + d) * NR + r] = e / sred[0];
}

// ---------------- k_emb (FROZEN GEMM) + fused fragment emission --------------
__global__ __launch_bounds__(256) void k_emb(const float* __restrict__ emb) {
    extern __shared__ __align__(16) float smem[];
    int b = blockIdx.z;
    int c0 = blockIdx.x * 128, d0 = blockIdx.y * 128;
    const float* P = g_P + (size_t)b * ND * NR;

    int tid = threadIdx.x;
    int tx = tid & 15, ty = tid >> 4;
    int arow = tid >> 1, ak = (tid & 1) << 3;
    int brow = tid >> 4, bcol = (tid & 15) << 3;

    unsigned sbase = (unsigned)__cvta_generic_to_shared(smem);
    unsigned aAddr0 = sbase + (unsigned)(ty * 8) * 4;
    unsigned bAddr0 = sbase + (unsigned)(2 * BK * LDSP + tx * 8) * 4;
    const unsigned bufStride = BK * LDSP * 4;

    const float* pa = P + (size_t)(d0 + arow) * NR + ak;
    const float* pb = emb + (size_t)brow * NC + c0 + bcol;

    unsigned long long acc[4][8];
#pragma unroll
    for (int p = 0; p < 4; p++)
#pragma unroll
        for (int j = 0; j < 8; j++) acc[p][j] = 0ull;

    float4 a0 = *(const float4*)(pa);
    float4 a1 = *(const float4*)(pa + 4);
    float4 b0 = *(const float4*)(pb);
    float4 b1 = *(const float4*)(pb + 4);
    {
        float av[8] = {a0.x, a0.y, a0.z, a0.w, a1.x, a1.y, a1.z, a1.w};
#pragma unroll
        for (int i = 0; i < 8; i++) smem[(ak + i) * LDSP + arow] = av[i];
        *(float4*)&smem[2 * BK * LDSP + brow * LDSP + bcol] = b0;
        *(float4*)&smem[2 * BK * LDSP + brow * LDSP + bcol + 4] = b1;
    }
    __syncthreads();

    const int NKT = NR / BK;
#pragma unroll 1
    for (int kt = 0; kt < NKT; kt++) {
        if (kt + 1 < NKT) {
            a0 = *(const float4*)(pa + (kt + 1) * BK);
            a1 = *(const float4*)(pa + (kt + 1) * BK + 4);
            b0 = *(const float4*)(pb + (size_t)(kt + 1) * BK * NC);
            b1 = *(const float4*)(pb + (size_t)(kt + 1) * BK * NC + 4);
        }
        unsigned off = (unsigned)(kt & 1) * bufStride;
        mma_tile(aAddr0 + off, bAddr0 + off, acc);
        if (kt + 1 < NKT) {
            int nb = (kt + 1) & 1;
            float* dA = smem + nb * BK * LDSP;
            float* dB = smem + (2 + nb) * BK * LDSP;
            float av[8] = {a0.x, a0.y, a0.z, a0.w, a1.x, a1.y, a1.z, a1.w};
#pragma unroll
            for (int i = 0; i < 8; i++) dA[(ak + i) * LDSP + arow] = av[i];
            *(float4*)&dB[brow * LDSP + bcol] = b0;
            *(float4*)&dB[brow * LDSP + bcol + 4] = b1;
            __syncthreads();
        }
    }

    // ---- epilogue 1: embT stores (unchanged values) + fragment staging ------
    __syncthreads();   // all warps done reading smem A/B
    uint32_t* fsm32 = (uint32_t*)smem;
    const int ksl = ty >> 1;      // local ks (0..7)
    const int half = ty & 1;      // 0 = lo 8 d (reg0), 1 = hi 8 d (reg1)

#pragma unroll
    for (int j = 0; j < 8; j++) {
        int c = c0 + tx * 8 + j;
        float v[8];
        unpack2(acc[0][j], v[0], v[1]);
        unpack2(acc[1][j], v[2], v[3]);
        unpack2(acc[2][j], v[4], v[5]);
        unpack2(acc[3][j], v[6], v[7]);
        float* dst = g_embT + ((size_t)b * NC + c) * ND + d0 + ty * 8;
        *(float4*)dst = make_float4(v[0], v[1], v[2], v[3]);
        *(float4*)(dst + 4) = make_float4(v[4], v[5], v[6], v[7]);
        // fragments: identical split3u of the identical bits
#pragma unroll
        for (int t = 0; t < 4; t++) {
            unsigned short he[3], ho[3];
            split3u(v[2 * t], he);
            split3u(v[2 * t + 1], ho);
#pragma unroll
            for (int s = 0; s < 3; s++) {
                unsigned w = (unsigned)he[s] | ((unsigned)ho[s] << 16);
                int elem = tx * CI_STRIDE + (ksl * 3 + s) * 32 + j * 4 + t;
                fsm32[elem * 2 + half] = w;
            }
        }
    }
    __syncthreads();

    // ---- epilogue 2: coalesced fragment copy to gmem (uint2: 8B-aligned) ----
    const int ci0 = c0 >> 3, ks0 = d0 >> 4;
#pragma unroll 1
    for (int i = tid; i < 16 * 768; i += 256) {     // uint2 units
        int cl = i >> 9 | 0;                        // i / 768
        cl = i / 768;
        int w = i - cl * 768;
        uint2 v = *(const uint2*)((const char*)smem + cl * (CI_STRIDE * 8) + w * 8);
        uint2* gdst = g_ebspF + (size_t)(b * 256 + ci0 + cl) * 1536 + (size_t)ks0 * 96;
        gdst[w] = v;
    }
}

// ---- A (pos) splits -> fragment-ordered gmem --------------------------------
__global__ void k_split_pos(const float* __restrict__ x) {
    int flat = blockIdx.x * 256 + threadIdx.x;
    int lane = flat & 31;
    int ks = (flat >> 5) & 15;
    int mi = (flat >> 9) & 255;
    int b = flat >> 17;
    int g = lane >> 2, t = lane & 3;
    int slo = mi * 16 + g;
    int k0 = ks * 16 + t * 2;
    const float* rlo = x + ((size_t)b * S1 + 1 + slo) * ND;
    const float* rhi = rlo + 8 * ND;
    float2 v0 = *(const float2*)(rlo + k0);
    float2 v1 = *(const float2*)(rhi + k0);
    float2 v2 = *(const float2*)(rlo + k0 + 8);
    float2 v3 = *(const float2*)(rhi + k0 + 8);
    float vals[4][2] = {{v0.x, v0.y}, {v1.x, v1.y}, {v2.x, v2.y}, {v3.x, v3.y}};
    unsigned w[3][4];
#pragma unroll
    for (int rg = 0; rg < 4; rg++) {
        unsigned short he[3], ho[3];
        split3u(vals[rg][0], he);
        split3u(vals[rg][1], ho);
#pragma unroll
        for (int s = 0; s < 3; s++) w[s][rg] = (unsigned)he[s] | ((unsigned)ho[s] << 16);
    }
    size_t base = ((((size_t)b * 256 + mi) * 16 + ks) * 3) * 32 + lane;
#pragma unroll
    for (int s = 0; s < 3; s++)
        g_pxspF[base + (size_t)s * 32] = make_uint4(w[s][0], w[s][1], w[s][2], w[s][3]);
}

// ---------------- e_sq / q_sq (FROZEN order) ---------------------------------
__global__ void k_esq() {
    int row = blockIdx.x * 8 + (threadIdx.x >> 5);
    int lane = threadIdx.x & 31;
    const float* p = g_embT + (size_t)row * ND;
    float s = 0.f;
#pragma unroll
    for (int i = lane; i < ND; i += 32) { float v = p[i]; s = fmaf(v, v, s); }
#pragma unroll
    for (int o = 16; o; o >>= 1) s += __shfl_xor_sync(0xffffffffu, s, o);
    if (lane == 0) g_esq[row] = s;
}

__global__ void k_qsq(const float* __restrict__ x) {
    int row = blockIdx.x * 8 + (threadIdx.x >> 5);
    int lane = threadIdx.x & 31;
    int b = row >> 12, s = row & (NS - 1);
    const float* p = x + ((size_t)b * S1 + 1 + s) * ND;
    float acc = 0.f;
#pragma unroll
    for (int i = lane; i < ND; i += 32) { float v = p[i]; acc = fmaf(v, v, acc); }
#pragma unroll
    for (int o = 16; o; o >>= 1) acc += __shfl_xor_sync(0xffffffffu, acc, o);
    if (lane == 0) g_qsq[row] = acc;
}

// ---------------- HMMA bf16-split dist GEMM + argmin (sliced) ----------------
__device__ __forceinline__ void mma16816(float* d, const uint32_t* a, const uint32_t* bb) {
    asm volatile(
        "mma.sync.aligned.m16n8k16.row.col.f32.bf16.bf16.f32 "
        "{%0,%1,%2,%3}, {%4,%5,%6,%7}, {%8,%9}, {%0,%1,%2,%3};"
        : "+f"(d[0]), "+f"(d[1]), "+f"(d[2]), "+f"(d[3])
        : "r"(a[0]), "r"(a[1]), "r"(a[2]), "r"(a[3]), "r"(bb[0]), "r"(bb[1]));
}
#define CP_ASYNC16(dst, src) \
    asm volatile("cp.async.ca.shared.global [%0], [%1], 16;" :: "r"(dst), "l"(src))
#define CP_COMMIT() asm volatile("cp.async.commit_group;" ::: "memory")
#define CP_WAIT0()  asm volatile("cp.async.wait_group 0;" ::: "memory")
#define CP_WAIT1()  asm volatile("cp.async.wait_group 1;" ::: "memory")

__global__ __launch_bounds__(256, 2) void k_argmin_mma() {
    extern __shared__ __align__(16) char sm[];
    unsigned sb = (unsigned)__cvta_generic_to_shared(sm);
    const int tid = threadIdx.x;
    const int lane = tid & 31, wid = tid >> 5;
    const int warpM = wid >> 2, warpN = wid & 3;
    const int g = lane >> 2, t = lane & 3;
    const int b = blockIdx.y;
    const int s0 = blockIdx.x * 128;
    const int slice = blockIdx.z;

    int bciJ[3];
    long boffJ[3];
    size_t constA[3];
#pragma unroll
    for (int j = 0; j < 3; j++) {
        int q = tid + j * 256;
        int amiJ = q / 96;
        int aoffJ = ((q / 32) % 3) * 32 + (q & 31);
        bciJ[j] = q / 48;
        boffJ[j] = (long)(((q / 16) % 3) * 32 + (q & 15) * 2);
        constA[j] = ((size_t)(b * 256 + (s0 >> 4) + amiJ)) * 1536 + aoffJ;
    }

    float qs[4][2], minv[4][2];
    int mini[4][2];
#pragma unroll
    for (int mt = 0; mt < 4; mt++)
#pragma unroll
        for (int h = 0; h < 2; h++) {
            qs[mt][h] = g_qsq[b * NS + s0 + warpM * 64 + mt * 16 + h * 8 + g];
            minv[mt][h] = FLT_MAX;
            mini[mt][h] = 0;
        }
    const float* esq = g_esq + b * NC;

    float acc[4][4][4];
#pragma unroll
    for (int mt = 0; mt < 4; mt++)
#pragma unroll
        for (int nt = 0; nt < 4; nt++)
#pragma unroll
            for (int r = 0; r < 4; r++) acc[mt][nt][r] = 0.f;

    auto load_stage = [&](int it2) {
        const int ct2 = slice * 2 + (it2 >> 4);
        const size_t ko = (size_t)(it2 & 15) * 96;
        const unsigned dst = (unsigned)(it2 % 3) * STAGE;
#pragma unroll
        for (int j = 0; j < 3; j++) {
            CP_ASYNC16(sb + dst + ((tid + j * 256) << 4),
                       (const char*)(g_pxspF + constA[j] + ko));
            size_t boff = ((size_t)(b * 256 + ct2 * 16 + bciJ[j])) * 1536 + boffJ[j] + ko;
            CP_ASYNC16(sb + dst + ABLK + ((tid + j * 256) << 4),
                       (const char*)(g_ebspF + boff));
        }
        CP_COMMIT();
    };
    auto loadA = [&](uint32_t af[4][4], unsigned buf, int sa) {
#pragma unroll
        for (int mt = 0; mt < 4; mt++) {
            unsigned ad = sb + buf + (unsigned)(((warpM * 4 + mt) * 3 + sa) << 9)
                        + (unsigned)(lane << 4);
            asm("ld.shared.v4.b32 {%0,%1,%2,%3}, [%4];"
                : "=r"(af[mt][0]), "=r"(af[mt][1]), "=r"(af[mt][2]), "=r"(af[mt][3])
                : "r"(ad));
        }
    };
    auto loadB = [&](uint32_t bf[4][2], unsigned buf, int sbp) {
#pragma unroll
        for (int nt = 0; nt < 4; nt++) {
            unsigned bd = sb + buf + ABLK
                        + (unsigned)(((warpN * 4 + nt) * 3 + sbp) << 8)
                        + (unsigned)(lane << 3);
            asm("ld.shared.v2.b32 {%0,%1}, [%2];"
                : "=r"(bf[nt][0]), "=r"(bf[nt][1]) : "r"(bd));
        }
    };
    auto mmaAll = [&](uint32_t af[4][4], uint32_t bf[4][2]) {
#pragma unroll
        for (int mt = 0; mt < 4; mt++)
#pragma unroll
            for (int nt = 0; nt < 4; nt++)
                mma16816(acc[mt][nt], af[mt], bf[nt]);
    };

    load_stage(0);
    load_stage(1);

#pragma unroll 1
    for (int it = 0; it < 32; it++) {
        if (it < 31) { CP_WAIT1(); } else { CP_WAIT0(); }
        __syncthreads();
        if (it + 2 < 32) load_stage(it + 2);

        const unsigned buf = (unsigned)(it % 3) * STAGE;
        uint32_t af[4][4], bf0[4][2], bfT[4][2];
        // pass order identical to R8..R13: (0,0)(0,1)(1,0)(1,1)(0,2)(2,0)
        loadB(bf0, buf, 0);
        loadB(bfT, buf, 1);
        loadA(af, buf, 0); mmaAll(af, bf0); mmaAll(af, bfT);
        loadA(af, buf, 1); mmaAll(af, bf0); mmaAll(af, bfT);
        loadB(bfT, buf, 2);
        loadA(af, buf, 0); mmaAll(af, bfT);
        loadA(af, buf, 2); mmaAll(af, bf0);

        if ((it & 15) == 15) {
            const int c0 = (slice * 2 + (it >> 4)) * 128;
#pragma unroll
            for (int nt = 0; nt < 4; nt++) {
                int ce = c0 + warpN * 32 + nt * 8 + t * 2;
                float2 e2 = *(const float2*)(esq + ce);
#pragma unroll
                for (int mt = 0; mt < 4; mt++)
#pragma unroll
                    for (int h = 0; h < 2; h++) {
                        float f0 = acc[mt][nt][h * 2 + 0];
                        float f1 = acc[mt][nt][h * 2 + 1];
                        float d0 = (qs[mt][h] - 2.f * f0) + e2.x;
                        float d1 = (qs[mt][h] - 2.f * f1) + e2.y;
                        if (d0 < minv[mt][h]) { minv[mt][h] = d0; mini[mt][h] = ce; }
                        if (d1 < minv[mt][h]) { minv[mt][h] = d1; mini[mt][h] = ce + 1; }
                    }
            }
#pragma unroll
            for (int mt = 0; mt < 4; mt++)
#pragma unroll
                for (int nt = 0; nt < 4; nt++)
#pragma unroll
                    for (int r = 0; r < 4; r++) acc[mt][nt][r] = 0.f;
        }
    }

    __syncthreads();
    float* rV = (float*)sm;
    int*   rI = (int*)(sm + 8192);
#pragma unroll
    for (int mt = 0; mt < 4; mt++)
#pragma unroll
        for (int h = 0; h < 2; h++) {
            int row = warpM * 64 + mt * 16 + h * 8 + g;
            int col = warpN * 4 + t;
            rV[row * 16 + col] = minv[mt][h];
            rI[row * 16 + col] = mini[mt][h];
        }
    __syncthreads();
    if (tid < 128) {
        float bv = rV[tid * 16]; int bi = rI[tid * 16];
#pragma unroll
        for (int k = 1; k < 16; k++) {
            float v = rV[tid * 16 + k]; int ii = rI[tid * 16 + k];
            if (v < bv || (v == bv && ii < bi)) { bv = v; bi = ii; }
        }
        size_t o = ((size_t)b * NS + s0 + tid) * NSLICE + slice;
        g_pminv[o] = bv;
        g_pmini[o] = bi;
    }
}

// ---------------- merge slices (ascending slice == ascending c) --------------
__global__ void k_merge() {
    int row = blockIdx.x * 256 + threadIdx.x;
    const float* pv = g_pminv + (size_t)row * NSLICE;
    const int*   pi = g_pmini + (size_t)row * NSLICE;
    float bv = pv[0]; int bi = pi[0];
#pragma unroll
    for (int s = 1; s < NSLICE; s++) {
        float v = pv[s]; int ii = pi[s];
        if (v < bv) { bv = v; bi = ii; }
    }
    g_idx[row] = bi;
}

// ---------------- gather + MSE + histogram -----------------------------------
__global__ void k_gather(const float* __restrict__ x, float* __restrict__ out) {
    int tkn = blockIdx.x;
    int b = tkn >> 12;
    int s = tkn & (NS - 1);
    int d = threadIdx.x;
    int idx = g_idx[tkn];
    float q = g_embT[((size_t)b * NC + idx) * ND + d];
    float p = x[((size_t)b * S1 + 1 + s) * ND + d];
    out[((size_t)b * S1 + 1 + s) * ND + d] = q;
    float diff = q - p;
    float v = diff * diff;
#pragma unroll
    for (int o = 16; o; o >>= 1) v += __shfl_xor_sync(0xffffffffu, v, o);
    __shared__ float sw[8];
    if ((d & 31) == 0) sw[d >> 5] = v;
    __syncthreads();
    if (d == 0) {
        float tot = 0.f;
#pragma unroll
        for (int i = 0; i < 8; i++) tot += sw[i];
        atomicAdd(&g_msep[blockIdx.x & 255], (double)tot);
        atomicAdd(&g_hist[b * NC + idx], 1);
    }
}

// ---------------- cls copy ---------------------------------------------------
__global__ void k_cls(const float* __restrict__ x, float* __restrict__ out) {
    int i = blockIdx.x * blockDim.x + threadIdx.x;
    int b = i >> 8, d = i & 255;
    out[(size_t)b * S1 * ND + d] = x[(size_t)b * S1 * ND + d];
}

// ---------------- finalize ---------------------------------------------------
__global__ void k_final(float* __restrict__ out) {
    int t = threadIdx.x;
    __shared__ double sd[256];
    sd[t] = g_msep[t];
    __syncthreads();
    for (int o = 128; o; o >>= 1) { if (t < o) sd[t] += sd[t + o]; __syncthreads(); }
    float mse = (float)(sd[0] / (double)((size_t)NB * NS * ND));

    __shared__ float sf[256];
    float pacc = 0.f;
    for (int b = 0; b < NB; b++) {
        float h = 0.f;
        for (int c = t; c < NC; c += 256) {
            float p = (float)g_hist[b * NC + c] / (float)NS;
            h += p * logf(p + 1e-10f);
        }
        sf[t] = h;
        __syncthreads();
        for (int o = 128; o; o >>= 1) { if (t < o) sf[t] += sf[t + o]; __syncthreads(); }
        if (t == 0) pacc += expf(-sf[0]);
        __syncthreads();
    }
    if (t == 0) {
        size_t Q = (size_t)NB * S1 * ND;
        out[Q + 0] = pacc / (float)NB;
        out[Q + 1] = mse;
        out[Q + 2] = mse;
        out[Q + 3] = fmaf(mse, 0.25f, mse);
    }
}

// ---------------- launch -----------------------------------------------------
extern "C" void kernel_launch(void* const* d_in, const int* in_sizes, int n_in,
                              void* d_out, int out_size) {
    const float* x     = (const float*)d_in[0];
    const float* emb   = (const float*)d_in[1];
    const float* cls_w = (const float*)d_in[2];
    const float* cls_b = (const float*)d_in[3];
    float* out = (float*)d_out;
    (void)in_sizes; (void)n_in; (void)out_size;

    cudaFuncSetAttribute(k_argmin_mma, cudaFuncAttributeMaxDynamicSharedMemorySize,
                         SMEM_MMA);
    cudaFuncSetAttribute(k_emb, cudaFuncAttributeMaxDynamicSharedMemorySize,
                         SMEM_EMBF);

    k_t<<<NB, NR>>>(x, cls_w);
    k_softmax<<<dim3(ND, NB), NR>>>(x, cls_b);
    k_emb<<<dim3(NC / 128, ND / 128, NB), 256, SMEM_EMBF>>>(emb);
    k_split_pos<<<4096, 256>>>(x);
    k_esq<<<NB * NC / 8, 256>>>();
    k_qsq<<<NB * NS / 8, 256>>>(x);
    k_argmin_mma<<<dim3(NS / 128, NB, NSLICE), 256, SMEM_MMA>>>();
    k_merge<<<NB * NS / 256, 256>>>();
    k_gather<<<NB * NS, 256>>>(x, out);
    k_cls<<<8, 256>>>(x, out);
    k_final<<<1, 256>>>(out);
}

// round 16
// speedup vs baseline: 1.0028x; 1.0028x over previous
#include <cuda_runtime.h>
#include <cuda_bf16.h>
#include <float.h>
#include <cstdint>

#define NB 8
#define NS 4096
#define ND 256
#define NR 512
#define NC 2048
#define S1 (NS + 1)

#define BK 16
#define LDSP 132

// ---- mma staging (bf16 3-split, 3 buffers) ----
#define ABLK 12288
#define BBLK 12288
#define STAGE (ABLK + BBLK)
#define SMEM_MMA (3 * STAGE)    // 73728

#define NSLICE 8                // c-slices per s-tile

// k_emb dynamic smem: GEMM region (33792B) vs fragment staging
#define CI_STRIDE 769           // uint2 elems per ci chunk (768 + 1 pad)
#define SMEM_EMBF (16 * CI_STRIDE * 8)   // 98432

// ---------------- scratch ----------------------------------------------------
__device__ float  g_t[NB * NR];
__device__ float  g_P[NB * ND * NR];
__device__ float  g_embT[(size_t)NB * NC * ND];
__device__ float  g_esq[NB * NC];
__device__ float  g_qsq[NB * NS];
__device__ int    g_hist[NB * NC];
__device__ double g_msep[256];
__device__ float  g_pminv[(size_t)NB * NS * NSLICE];
__device__ int    g_pmini[(size_t)NB * NS * NSLICE];
// fragment-ordered bf16 splits: A (pos) 16B/lane, B (embT) 8B/lane
__device__ uint4  g_pxspF[(size_t)NB * 256 * 16 * 3 * 32];
__device__ uint2  g_ebspF[(size_t)NB * 256 * 16 * 3 * 32];

// ---------------- f32x2 helpers (k_emb) --------------------------------------
__device__ __forceinline__ unsigned long long pack2(float lo, float hi) {
    unsigned long long r;
    asm("mov.b64 %0, {%1, %2};" : "=l"(r) : "f"(lo), "f"(hi));
    return r;
}
__device__ __forceinline__ void unpack2(unsigned long long v, float& lo, float& hi) {
    asm("mov.b64 {%0, %1}, %2;" : "=f"(lo), "=f"(hi) : "l"(v));
}
#define FMA2(d, a, b) asm("fma.rn.f32x2 %0, %1, %2, %0;" : "+l"(d) : "l"(a), "l"(b))

__device__ __forceinline__ void mma_tile(unsigned aAddr, unsigned bAddr,
                                         unsigned long long acc[4][8]) {
#pragma unroll
    for (int kk = 0; kk < BK; kk++) {
        unsigned long long a01, a23, a45, a67;
        asm("ld.shared.v2.b64 {%0,%1}, [%2];"
            : "=l"(a01), "=l"(a23) : "r"(aAddr + kk * (LDSP * 4)));
        asm("ld.shared.v2.b64 {%0,%1}, [%2];"
            : "=l"(a45), "=l"(a67) : "r"(aAddr + kk * (LDSP * 4) + 16));
        float b0, b1, b2, b3, b4, b5, b6, b7;
        asm("ld.shared.v4.b32 {%0,%1,%2,%3}, [%4];"
            : "=f"(b0), "=f"(b1), "=f"(b2), "=f"(b3) : "r"(bAddr + kk * (LDSP * 4)));
        asm("ld.shared.v4.b32 {%0,%1,%2,%3}, [%4];"
            : "=f"(b4), "=f"(b5), "=f"(b6), "=f"(b7) : "r"(bAddr + kk * (LDSP * 4) + 16));
        float bs[8] = {b0, b1, b2, b3, b4, b5, b6, b7};
#pragma unroll
        for (int j = 0; j < 8; j++) {
            unsigned long long bb = pack2(bs[j], bs[j]);
            FMA2(acc[0][j], a01, bb);
            FMA2(acc[1][j], a23, bb);
            FMA2(acc[2][j], a45, bb);
            FMA2(acc[3][j], a67, bb);
        }
    }
}

// ---------------- bf16 3-way split helpers -----------------------------------
__device__ __forceinline__ void split3u(float v, unsigned short h[3]) {
    __nv_bfloat16 b1 = __float2bfloat16(v);
    float r = v - __bfloat162float(b1);
    __nv_bfloat16 b2 = __float2bfloat16(r);
    float r2 = r - __bfloat162float(b2);
    __nv_bfloat16 b3 = __float2bfloat16(r2);
    h[0] = __bfloat16_as_ushort(b1);
    h[1] = __bfloat16_as_ushort(b2);
    h[2] = __bfloat16_as_ushort(b3);
}

// ---------------- t[b,r] + zero fold -----------------------------------------
__global__ void k_t(const float* __restrict__ x, const float* __restrict__ cls_w) {
    int b = blockIdx.x;
    int r = threadIdx.x;
    int gt = b * NR + r;
    for (int i = gt; i < NB * NC; i += NB * NR) g_hist[i] = 0;
    if (gt < 256) g_msep[gt] = 0.0;

    __shared__ float cls[ND];
    if (r < ND) cls[r] = x[(size_t)b * S1 * ND + r];
    __syncthreads();
    float acc = 0.f;
#pragma unroll 8
    for (int d = 0; d < ND; d++) acc = fmaf(cls[d], cls_w[d * NR + r], acc);
    g_t[b * NR + r] = acc;
}

// ---------------- softmax (FROZEN) -------------------------------------------
__global__ void k_softmax(const float* __restrict__ x, const float* __restrict__ cls_b) {
    int d = blockIdx.x, b = blockIdx.y;
    int r = threadIdx.x;
    float clsd = x[(size_t)b * S1 * ND + d];
    float logit = fmaf(clsd, g_t[b * NR + r], cls_b[r]);

    __shared__ float sred[16];
    float m = logit;
#pragma unroll
    for (int o = 16; o; o >>= 1) m = fmaxf(m, __shfl_xor_sync(0xffffffffu, m, o));
    if ((r & 31) == 0) sred[r >> 5] = m;
    __syncthreads();
    if (r < 32) {
        float v = (r < 16) ? sred[r] : -FLT_MAX;
#pragma unroll
        for (int o = 16; o; o >>= 1) v = fmaxf(v, __shfl_xor_sync(0xffffffffu, v, o));
        if (r == 0) sred[0] = v;
    }
    __syncthreads();
    m = sred[0];
    float e = expf(logit - m);
    __syncthreads();
    float s = e;
#pragma unroll
    for (int o = 16; o; o >>= 1) s += __shfl_xor_sync(0xffffffffu, s, o);
    if ((r & 31) == 0) sred[r >> 5] = s;
    __syncthreads();
    if (r < 32) {
        float v = (r < 16) ? sred[r] : 0.f;
#pragma unroll
        for (int o = 16; o; o >>= 1) v += __shfl_xor_sync(0xffffffffu, v, o);
        if (r == 0) sred[0] = v;
    }
    __syncthreads();
    g_P[((size_t)b * ND + d) * NR + r] = e / sred[0];
}

// ---------------- k_emb (FROZEN GEMM) + fused fragment emission --------------
__global__ __launch_bounds__(256) void k_emb(const float* __restrict__ emb) {
    extern __shared__ __align__(16) float smem[];
    int b = blockIdx.z;
    int c0 = blockIdx.x * 128, d0 = blockIdx.y * 128;
    const float* P = g_P + (size_t)b * ND * NR;

    int tid = threadIdx.x;
    int tx = tid & 15, ty = tid >> 4;
    int arow = tid >> 1, ak = (tid & 1) << 3;
    int brow = tid >> 4, bcol = (tid & 15) << 3;

    unsigned sbase = (unsigned)__cvta_generic_to_shared(smem);
    unsigned aAddr0 = sbase + (unsigned)(ty * 8) * 4;
    unsigned bAddr0 = sbase + (unsigned)(2 * BK * LDSP + tx * 8) * 4;
    const unsigned bufStride = BK * LDSP * 4;

    const float* pa = P + (size_t)(d0 + arow) * NR + ak;
    const float* pb = emb + (size_t)brow * NC + c0 + bcol;

    unsigned long long acc[4][8];
#pragma unroll
    for (int p = 0; p < 4; p++)
#pragma unroll
        for (int j = 0; j < 8; j++) acc[p][j] = 0ull;

    float4 a0 = *(const float4*)(pa);
    float4 a1 = *(const float4*)(pa + 4);
    float4 b0 = *(const float4*)(pb);
    float4 b1 = *(const float4*)(pb + 4);
    {
        float av[8] = {a0.x, a0.y, a0.z, a0.w, a1.x, a1.y, a1.z, a1.w};
#pragma unroll
        for (int i = 0; i < 8; i++) smem[(ak + i) * LDSP + arow] = av[i];
        *(float4*)&smem[2 * BK * LDSP + brow * LDSP + bcol] = b0;
        *(float4*)&smem[2 * BK * LDSP + brow * LDSP + bcol + 4] = b1;
    }
    __syncthreads();

    const int NKT = NR / BK;
#pragma unroll 1
    for (int kt = 0; kt < NKT; kt++) {
        if (kt + 1 < NKT) {
            a0 = *(const float4*)(pa + (kt + 1) * BK);
            a1 = *(const float4*)(pa + (kt + 1) * BK + 4);
            b0 = *(const float4*)(pb + (size_t)(kt + 1) * BK * NC);
            b1 = *(const float4*)(pb + (size_t)(kt + 1) * BK * NC + 4);
        }
        unsigned off = (unsigned)(kt & 1) * bufStride;
        mma_tile(aAddr0 + off, bAddr0 + off, acc);
        if (kt + 1 < NKT) {
            int nb = (kt + 1) & 1;
            float* dA = smem + nb * BK * LDSP;
            float* dB = smem + (2 + nb) * BK * LDSP;
            float av[8] = {a0.x, a0.y, a0.z, a0.w, a1.x, a1.y, a1.z, a1.w};
#pragma unroll
            for (int i = 0; i < 8; i++) dA[(ak + i) * LDSP + arow] = av[i];
            *(float4*)&dB[brow * LDSP + bcol] = b0;
            *(float4*)&dB[brow * LDSP + bcol + 4] = b1;
            __syncthreads();
        }
    }

    // ---- epilogue 1: embT stores (unchanged values) + fragment staging ------
    __syncthreads();
    uint32_t* fsm32 = (uint32_t*)smem;
    const int ksl = ty >> 1;
    const int half = ty & 1;

#pragma unroll
    for (int j = 0; j < 8; j++) {
        int c = c0 + tx * 8 + j;
        float v[8];
        unpack2(acc[0][j], v[0], v[1]);
        unpack2(acc[1][j], v[2], v[3]);
        unpack2(acc[2][j], v[4], v[5]);
        unpack2(acc[3][j], v[6], v[7]);
        float* dst = g_embT + ((size_t)b * NC + c) * ND + d0 + ty * 8;
        *(float4*)dst = make_float4(v[0], v[1], v[2], v[3]);
        *(float4*)(dst + 4) = make_float4(v[4], v[5], v[6], v[7]);
#pragma unroll
        for (int t = 0; t < 4; t++) {
            unsigned short he[3], ho[3];
            split3u(v[2 * t], he);
            split3u(v[2 * t + 1], ho);
#pragma unroll
            for (int s = 0; s < 3; s++) {
                unsigned w = (unsigned)he[s] | ((unsigned)ho[s] << 16);
                int elem = tx * CI_STRIDE + (ksl * 3 + s) * 32 + j * 4 + t;
                fsm32[elem * 2 + half] = w;
            }
        }
    }
    __syncthreads();

    // ---- epilogue 2: fragment copy to gmem (uint2 = 8B aligned) -------------
    const int ci0 = c0 >> 3, ks0 = d0 >> 4;
#pragma unroll 1
    for (int i = tid; i < 16 * 768; i += 256) {
        int cl = i / 768;
        int w = i - cl * 768;
        uint2 v = *(const uint2*)((const char*)smem + cl * (CI_STRIDE * 8) + w * 8);
        uint2* gdst = g_ebspF + (size_t)(b * 256 + ci0 + cl) * 1536 + (size_t)ks0 * 96;
        gdst[w] = v;
    }
}

// ---- A (pos) splits + FROZEN qsq, fused by grid branch ----------------------
__global__ void k_split_pos_qsq(const float* __restrict__ x) {
    if (blockIdx.x < 4096) {
        // ---- split_pos (unchanged) ----
        int flat = blockIdx.x * 256 + threadIdx.x;
        int lane = flat & 31;
        int ks = (flat >> 5) & 15;
        int mi = (flat >> 9) & 255;
        int b = flat >> 17;
        int g = lane >> 2, t = lane & 3;
        int slo = mi * 16 + g;
        int k0 = ks * 16 + t * 2;
        const float* rlo = x + ((size_t)b * S1 + 1 + slo) * ND;
        const float* rhi = rlo + 8 * ND;
        float2 v0 = *(const float2*)(rlo + k0);
        float2 v1 = *(const float2*)(rhi + k0);
        float2 v2 = *(const float2*)(rlo + k0 + 8);
        float2 v3 = *(const float2*)(rhi + k0 + 8);
        float vals[4][2] = {{v0.x, v0.y}, {v1.x, v1.y}, {v2.x, v2.y}, {v3.x, v3.y}};
        unsigned w[3][4];
#pragma unroll
        for (int rg = 0; rg < 4; rg++) {
            unsigned short he[3], ho[3];
            split3u(vals[rg][0], he);
            split3u(vals[rg][1], ho);
#pragma unroll
            for (int s = 0; s < 3; s++) w[s][rg] = (unsigned)he[s] | ((unsigned)ho[s] << 16);
        }
        size_t base = ((((size_t)b * 256 + mi) * 16 + ks) * 3) * 32 + lane;
#pragma unroll
        for (int s = 0; s < 3; s++)
            g_pxspF[base + (size_t)s * 32] = make_uint4(w[s][0], w[s][1], w[s][2], w[s][3]);
    } else {
        // ---- qsq (FROZEN: identical loop/shuffle order) ----
        int row = (blockIdx.x - 4096) * 8 + (threadIdx.x >> 5);
        int lane = threadIdx.x & 31;
        int b = row >> 12, s = row & (NS - 1);
        const float* p = x + ((size_t)b * S1 + 1 + s) * ND;
        float acc = 0.f;
#pragma unroll
        for (int i = lane; i < ND; i += 32) { float v = p[i]; acc = fmaf(v, v, acc); }
#pragma unroll
        for (int o = 16; o; o >>= 1) acc += __shfl_xor_sync(0xffffffffu, acc, o);
        if (lane == 0) g_qsq[row] = acc;
    }
}

// ---------------- e_sq (FROZEN order) ----------------------------------------
__global__ void k_esq() {
    int row = blockIdx.x * 8 + (threadIdx.x >> 5);
    int lane = threadIdx.x & 31;
    const float* p = g_embT + (size_t)row * ND;
    float s = 0.f;
#pragma unroll
    for (int i = lane; i < ND; i += 32) { float v = p[i]; s = fmaf(v, v, s); }
#pragma unroll
    for (int o = 16; o; o >>= 1) s += __shfl_xor_sync(0xffffffffu, s, o);
    if (lane == 0) g_esq[row] = s;
}

// ---------------- HMMA bf16-split dist GEMM + argmin (sliced) ----------------
__device__ __forceinline__ void mma16816(float* d, const uint32_t* a, const uint32_t* bb) {
    asm volatile(
        "mma.sync.aligned.m16n8k16.row.col.f32.bf16.bf16.f32 "
        "{%0,%1,%2,%3}, {%4,%5,%6,%7}, {%8,%9}, {%0,%1,%2,%3};"
        : "+f"(d[0]), "+f"(d[1]), "+f"(d[2]), "+f"(d[3])
        : "r"(a[0]), "r"(a[1]), "r"(a[2]), "r"(a[3]), "r"(bb[0]), "r"(bb[1]));
}
#define CP_ASYNC16(dst, src) \
    asm volatile("cp.async.ca.shared.global [%0], [%1], 16;" :: "r"(dst), "l"(src))
#define CP_COMMIT() asm volatile("cp.async.commit_group;" ::: "memory")
#define CP_WAIT0()  asm volatile("cp.async.wait_group 0;" ::: "memory")
#define CP_WAIT1()  asm volatile("cp.async.wait_group 1;" ::: "memory")

__global__ __launch_bounds__(256, 2) void k_argmin_mma() {
    extern __shared__ __align__(16) char sm[];
    unsigned sb = (unsigned)__cvta_generic_to_shared(sm);
    const int tid = threadIdx.x;
    const int lane = tid & 31, wid = tid >> 5;
    const int warpM = wid >> 2, warpN = wid & 3;
    const int g = lane >> 2, t = lane & 3;
    const int b = blockIdx.y;
    const int s0 = blockIdx.x * 128;
    const int slice = blockIdx.z;

    int bciJ[3];
    long boffJ[3];
    size_t constA[3];
#pragma unroll
    for (int j = 0; j < 3; j++) {
        int q = tid + j * 256;
        int amiJ = q / 96;
        int aoffJ = ((q / 32) % 3) * 32 + (q & 31);
        bciJ[j] = q / 48;
        boffJ[j] = (long)(((q / 16) % 3) * 32 + (q & 15) * 2);
        constA[j] = ((size_t)(b * 256 + (s0 >> 4) + amiJ)) * 1536 + aoffJ;
    }

    float qs[4][2], minv[4][2];
    int mini[4][2];
#pragma unroll
    for (int mt = 0; mt < 4; mt++)
#pragma unroll
        for (int h = 0; h < 2; h++) {
            qs[mt][h] = g_qsq[b * NS + s0 + warpM * 64 + mt * 16 + h * 8 + g];
            minv[mt][h] = FLT_MAX;
            mini[mt][h] = 0;
        }
    const float* esq = g_esq + b * NC;

    float acc[4][4][4];
#pragma unroll
    for (int mt = 0; mt < 4; mt++)
#pragma unroll
        for (int nt = 0; nt < 4; nt++)
#pragma unroll
            for (int r = 0; r < 4; r++) acc[mt][nt][r] = 0.f;

    auto load_stage = [&](int it2) {
        const int ct2 = slice * 2 + (it2 >> 4);
        const size_t ko = (size_t)(it2 & 15) * 96;
        const unsigned dst = (unsigned)(it2 % 3) * STAGE;
#pragma unroll
        for (int j = 0; j < 3; j++) {
            CP_ASYNC16(sb + dst + ((tid + j * 256) << 4),
                       (const char*)(g_pxspF + constA[j] + ko));
            size_t boff = ((size_t)(b * 256 + ct2 * 16 + bciJ[j])) * 1536 + boffJ[j] + ko;
            CP_ASYNC16(sb + dst + ABLK + ((tid + j * 256) << 4),
                       (const char*)(g_ebspF + boff));
        }
        CP_COMMIT();
    };
    auto loadA = [&](uint32_t af[4][4], unsigned buf, int sa) {
#pragma unroll
        for (int mt = 0; mt < 4; mt++) {
            unsigned ad = sb + buf + (unsigned)(((warpM * 4 + mt) * 3 + sa) << 9)
                        + (unsigned)(lane << 4);
            asm("ld.shared.v4.b32 {%0,%1,%2,%3}, [%4];"
                : "=r"(af[mt][0]), "=r"(af[mt][1]), "=r"(af[mt][2]), "=r"(af[mt][3])
                : "r"(ad));
        }
    };
    auto loadB = [&](uint32_t bf[4][2], unsigned buf, int sbp) {
#pragma unroll
        for (int nt = 0; nt < 4; nt++) {
            unsigned bd = sb + buf + ABLK
                        + (unsigned)(((warpN * 4 + nt) * 3 + sbp) << 8)
                        + (unsigned)(lane << 3);
            asm("ld.shared.v2.b32 {%0,%1}, [%2];"
                : "=r"(bf[nt][0]), "=r"(bf[nt][1]) : "r"(bd));
        }
    };
    auto mmaAll = [&](uint32_t af[4][4], uint32_t bf[4][2]) {
#pragma unroll
        for (int mt = 0; mt < 4; mt++)
#pragma unroll
            for (int nt = 0; nt < 4; nt++)
                mma16816(acc[mt][nt], af[mt], bf[nt]);
    };

    load_stage(0);
    load_stage(1);

#pragma unroll 1
    for (int it = 0; it < 32; it++) {
        if (it < 31) { CP_WAIT1(); } else { CP_WAIT0(); }
        __syncthreads();
        if (it + 2 < 32) load_stage(it + 2);

        const unsigned buf = (unsigned)(it % 3) * STAGE;
        uint32_t af[4][4], bf0[4][2], bfT[4][2];
        // pass order identical to R8..R15: (0,0)(0,1)(1,0)(1,1)(0,2)(2,0)
        loadB(bf0, buf, 0);
        loadB(bfT, buf, 1);
        loadA(af, buf, 0); mmaAll(af, bf0); mmaAll(af, bfT);
        loadA(af, buf, 1); mmaAll(af, bf0); mmaAll(af, bfT);
        loadB(bfT, buf, 2);
        loadA(af, buf, 0); mmaAll(af, bfT);
        loadA(af, buf, 2); mmaAll(af, bf0);

        if ((it & 15) == 15) {
            const int c0 = (slice * 2 + (it >> 4)) * 128;
#pragma unroll
            for (int nt = 0; nt < 4; nt++) {
                int ce = c0 + warpN * 32 + nt * 8 + t * 2;
                float2 e2 = *(const float2*)(esq + ce);
#pragma unroll
                for (int mt = 0; mt < 4; mt++)
#pragma unroll
                    for (int h = 0; h < 2; h++) {
                        float f0 = acc[mt][nt][h * 2 + 0];
                        float f1 = acc[mt][nt][h * 2 + 1];
                        float d0 = (qs[mt][h] - 2.f * f0) + e2.x;
                        float d1 = (qs[mt][h] - 2.f * f1) + e2.y;
                        if (d0 < minv[mt][h]) { minv[mt][h] = d0; mini[mt][h] = ce; }
                        if (d1 < minv[mt][h]) { minv[mt][h] = d1; mini[mt][h] = ce + 1; }
                    }
            }
#pragma unroll
            for (int mt = 0; mt < 4; mt++)
#pragma unroll
                for (int nt = 0; nt < 4; nt++)
#pragma unroll
                    for (int r = 0; r < 4; r++) acc[mt][nt][r] = 0.f;
        }
    }

    __syncthreads();
    float* rV = (float*)sm;
    int*   rI = (int*)(sm + 8192);
#pragma unroll
    for (int mt = 0; mt < 4; mt++)
#pragma unroll
        for (int h = 0; h < 2; h++) {
            int row = warpM * 64 + mt * 16 + h * 8 + g;
            int col = warpN * 4 + t;
            rV[row * 16 + col] = minv[mt][h];
            rI[row * 16 + col] = mini[mt][h];
        }
    __syncthreads();
    if (tid < 128) {
        float bv = rV[tid * 16]; int bi = rI[tid * 16];
#pragma unroll
        for (int k = 1; k < 16; k++) {
            float v = rV[tid * 16 + k]; int ii = rI[tid * 16 + k];
            if (v < bv || (v == bv && ii < bi)) { bv = v; bi = ii; }
        }
        size_t o = ((size_t)b * NS + s0 + tid) * NSLICE + slice;
        g_pminv[o] = bv;
        g_pmini[o] = bi;
    }
}

// -------- gather (+ inline slice merge) + cls copy, fused by grid branch -----
__global__ void k_gather(const float* __restrict__ x, float* __restrict__ out) {
    int tkn = blockIdx.x;
    if (tkn >= NB * NS) {
        // cls copy: 8 blocks, one per batch row
        int b = tkn - NB * NS;
        int d = threadIdx.x;
        out[(size_t)b * S1 * ND + d] = x[(size_t)b * S1 * ND + d];
        return;
    }
    int b = tkn >> 12;
    int s = tkn & (NS - 1);
    int d = threadIdx.x;

    // inline merge (ascending slice == ascending c; ties keep earlier slice)
    const float* pv = g_pminv + (size_t)tkn * NSLICE;
    const int*   pi = g_pmini + (size_t)tkn * NSLICE;
    float bv = pv[0]; int idx = pi[0];
#pragma unroll
    for (int sl = 1; sl < NSLICE; sl++) {
        float v = pv[sl]; int ii = pi[sl];
        if (v < bv) { bv = v; idx = ii; }
    }

    float q = g_embT[((size_t)b * NC + idx) * ND + d];
    float p = x[((size_t)b * S1 + 1 + s) * ND + d];
    out[((size_t)b * S1 + 1 + s) * ND + d] = q;
    float diff = q - p;
    float v = diff * diff;
#pragma unroll
    for (int o = 16; o; o >>= 1) v += __shfl_xor_sync(0xffffffffu, v, o);
    __shared__ float sw[8];
    if ((d & 31) == 0) sw[d >> 5] = v;
    __syncthreads();
    if (d == 0) {
        float tot = 0.f;
#pragma unroll
        for (int i = 0; i < 8; i++) tot += sw[i];
        atomicAdd(&g_msep[blockIdx.x & 255], (double)tot);
        atomicAdd(&g_hist[b * NC + idx], 1);
    }
}

// ---------------- finalize ---------------------------------------------------
__global__ void k_final(float* __restrict__ out) {
    int t = threadIdx.x;
    __shared__ double sd[256];
    sd[t] = g_msep[t];
    __syncthreads();
    for (int o = 128; o; o >>= 1) { if (t < o) sd[t] += sd[t + o]; __syncthreads(); }
    float mse = (float)(sd[0] / (double)((size_t)NB * NS * ND));

    __shared__ float sf[256];
    float pacc = 0.f;
    for (int b = 0; b < NB; b++) {
        float h = 0.f;
        for (int c = t; c < NC; c += 256) {
            float p = (float)g_hist[b * NC + c] / (float)NS;
            h += p * logf(p + 1e-10f);
        }
        sf[t] = h;
        __syncthreads();
        for (int o = 128; o; o >>= 1) { if (t < o) sf[t] += sf[t + o]; __syncthreads(); }
        if (t == 0) pacc += expf(-sf[0]);
        __syncthreads();
    }
    if (t == 0) {
        size_t Q = (size_t)NB * S1 * ND;
        out[Q + 0] = pacc / (float)NB;
        out[Q + 1] = mse;
        out[Q + 2] = mse;
        out[Q + 3] = fmaf(mse, 0.25f, mse);
    }
}

// ---------------- launch -----------------------------------------------------
extern "C" void kernel_launch(void* const* d_in, const int* in_sizes, int n_in,
                              void* d_out, int out_size) {
    const float* x     = (const float*)d_in[0];
    const float* emb   = (const float*)d_in[1];
    const float* cls_w = (const float*)d_in[2];
    const float* cls_b = (const float*)d_in[3];
    float* out = (float*)d_out;
    (void)in_sizes; (void)n_in; (void)out_size;

    cudaFuncSetAttribute(k_argmin_mma, cudaFuncAttributeMaxDynamicSharedMemorySize,
                         SMEM_MMA);
    cudaFuncSetAttribute(k_emb, cudaFuncAttributeMaxDynamicSharedMemorySize,
                         SMEM_EMBF);

    k_t<<<NB, NR>>>(x, cls_w);
    k_softmax<<<dim3(ND, NB), NR>>>(x, cls_b);
    k_emb<<<dim3(NC / 128, ND / 128, NB), 256, SMEM_EMBF>>>(emb);
    k_split_pos_qsq<<<8192, 256>>>(x);
    k_esq<<<NB * NC / 8, 256>>>();
    k_argmin_mma<<<dim3(NS / 128, NB, NSLICE), 256, SMEM_MMA>>>();
    k_gather<<<NB * NS + NB, 256>>>(x, out);
    k_final<<<1, 256>>>(out);
}